// round 1
// baseline (speedup 1.0000x reference)
#include <cuda_runtime.h>
#include <math.h>

#define BB 4
#define NN 4096
#define DKK 64
#define MT 32                       // Fourier modes
#define THALF 8.0                   // half-period T
#define OMEGA1 0.39269908169872414f // pi/8
#define TILE 128
#define NBLK 128                    // BB*NN/TILE
#define FSTRIDE 132                 // per-mode feature row: C[64], S[64], cc, ss, pad2
#define FLEN (MT*FSTRIDE)           // 4224

struct CoefArg { float a[MT]; };

__device__ __align__(16) float g_Q[BB*NN];
__device__ __align__(16) float g_part[(size_t)NBLK*FLEN];
__device__ __align__(16) float g_feat[BB*FLEN];

// ---------------------------------------------------------------------------
// K1: per-tile QKV + Fourier feature partial sums
// ---------------------------------------------------------------------------
__global__ __launch_bounds__(256) void k_feat(
    const float* __restrict__ x, const float* __restrict__ Wv,
    const float* __restrict__ bv, const float* __restrict__ wq,
    const float* __restrict__ wk)
{
    extern __shared__ float sm[];
    float* xs   = sm;                    // TILE*65
    float* Wvt  = xs  + TILE*65;         // 64*68 (transposed, padded)
    float* Vs   = Wvt + 64*68;           // TILE*68
    float* cosT = Vs  + TILE*68;         // MT*129
    float* sinT = cosT + MT*129;         // MT*129
    float* wqs  = sinT + MT*129;         // 64
    float* wks  = wqs + 64;              // 64
    float* bvs  = wks + 64;              // 64

    const int t = threadIdx.x;
    const int blk = blockIdx.x;
    const int b = blk >> 5, tile = blk & 31;
    const float* xt = x + ((size_t)b*NN + (size_t)tile*TILE) * DKK;

    // stage x tile (padded rows, stride 65 -> conflict-free scalar access)
    for (int i = t; i < TILE*DKK; i += 256)
        xs[(i >> 6)*65 + (i & 63)] = xt[i];
    // stage Wv transposed: Wvt[d][e] = Wv[e][d], row stride 68 (16B-aligned rows)
    for (int i = t; i < DKK*DKK; i += 256)
        Wvt[(i & 63)*68 + (i >> 6)] = Wv[i];
    if (t < DKK) { wqs[t] = wq[t]; wks[t] = wk[t]; bvs[t] = bv[t]; }
    __syncthreads();

    // per-token scalars Q,K + cos/sin tables via rotation recurrence
    if (t < TILE) {
        float q = 0.f, k = 0.f;
        #pragma unroll 16
        for (int d = 0; d < DKK; d++) {
            float xv = xs[t*65 + d];
            q = fmaf(xv, wqs[d], q);
            k = fmaf(xv, wks[d], k);
        }
        g_Q[(size_t)b*NN + (size_t)tile*TILE + t] = q;
        float s1, c1;
        __sincosf(OMEGA1 * k, &s1, &c1);
        float c = 1.f, s = 0.f;
        #pragma unroll
        for (int m = 0; m < MT; m++) {
            cosT[m*129 + t] = c;
            sinT[m*129 + t] = s;
            float cn = c*c1 - s*s1;
            s = fmaf(s, c1, c*s1);
            c = cn;
        }
    }

    // V = x @ Wv^T + bv  (thread: token j = t>>1, half dh = t&1 owns 32 outputs)
    {
        const int j = t >> 1, dh = t & 1;
        float acc[32];
        #pragma unroll
        for (int i = 0; i < 32; i++) acc[i] = bvs[dh*32 + i];
        #pragma unroll 4
        for (int d2 = 0; d2 < DKK; d2++) {
            float xv = xs[j*65 + d2];
            const float4* wrow = (const float4*)&Wvt[d2*68 + dh*32];
            #pragma unroll
            for (int i4 = 0; i4 < 8; i4++) {
                float4 w4 = wrow[i4];
                acc[i4*4+0] = fmaf(xv, w4.x, acc[i4*4+0]);
                acc[i4*4+1] = fmaf(xv, w4.y, acc[i4*4+1]);
                acc[i4*4+2] = fmaf(xv, w4.z, acc[i4*4+2]);
                acc[i4*4+3] = fmaf(xv, w4.w, acc[i4*4+3]);
            }
        }
        float4* vrow = (float4*)&Vs[j*68 + dh*32];
        #pragma unroll
        for (int i4 = 0; i4 < 8; i4++)
            vrow[i4] = make_float4(acc[i4*4+0], acc[i4*4+1], acc[i4*4+2], acc[i4*4+3]);
    }
    __syncthreads();

    // feature rank-update: thread = (d4 in 0..15, mslot in 0..15), 2 modes each
    {
        const int d4 = t & 15, mslot = t >> 4;
        const int m0 = mslot * 2;
        float aC[2][4] = {{0,0,0,0},{0,0,0,0}};
        float aS[2][4] = {{0,0,0,0},{0,0,0,0}};
        float aCC[2] = {0,0}, aSS[2] = {0,0};
        for (int j = 0; j < TILE; j++) {
            float4 v = *(const float4*)&Vs[j*68 + d4*4];
            #pragma unroll
            for (int mi = 0; mi < 2; mi++) {
                float c = cosT[(m0+mi)*129 + j];
                float s = sinT[(m0+mi)*129 + j];
                aC[mi][0] = fmaf(c, v.x, aC[mi][0]);
                aC[mi][1] = fmaf(c, v.y, aC[mi][1]);
                aC[mi][2] = fmaf(c, v.z, aC[mi][2]);
                aC[mi][3] = fmaf(c, v.w, aC[mi][3]);
                aS[mi][0] = fmaf(s, v.x, aS[mi][0]);
                aS[mi][1] = fmaf(s, v.y, aS[mi][1]);
                aS[mi][2] = fmaf(s, v.z, aS[mi][2]);
                aS[mi][3] = fmaf(s, v.w, aS[mi][3]);
                if (d4 == 0) { aCC[mi] += c; aSS[mi] += s; }
            }
        }
        float* pp = g_part + (size_t)blk * FLEN;
        #pragma unroll
        for (int mi = 0; mi < 2; mi++) {
            float* bse = pp + (m0+mi)*FSTRIDE;
            *(float4*)&bse[d4*4]      = make_float4(aC[mi][0], aC[mi][1], aC[mi][2], aC[mi][3]);
            *(float4*)&bse[64 + d4*4] = make_float4(aS[mi][0], aS[mi][1], aS[mi][2], aS[mi][3]);
            if (d4 == 0) { bse[128] = aCC[mi]; bse[129] = aSS[mi]; }
        }
    }
}

// ---------------------------------------------------------------------------
// K1b: reduce 32 tile-partials per batch (deterministic, no atomics)
// ---------------------------------------------------------------------------
__global__ __launch_bounds__(256) void k_reduce()
{
    int f = blockIdx.x * 256 + threadIdx.x;
    int b = blockIdx.y;
    if (f >= FLEN) return;
    float s = 0.f;
    #pragma unroll 8
    for (int tb = 0; tb < 32; tb++)
        s += g_part[(size_t)(b*32 + tb)*FLEN + f];
    g_feat[b*FLEN + f] = s;
}

// ---------------------------------------------------------------------------
// K2: per-token output = softmax-weighted V-sum (via features) + residual + LN
// ---------------------------------------------------------------------------
__global__ __launch_bounds__(256) void k_out(
    const float* __restrict__ x, const float* __restrict__ gamma,
    const float* __restrict__ beta, float* __restrict__ out, CoefArg ca)
{
    extern __shared__ float sm[];
    float* fs = sm;            // FLEN
    float* gs = fs + FLEN;     // 64
    float* bs = gs + 64;       // 64

    const int t = threadIdx.x;
    const int blk = blockIdx.x;
    const int b = blk >> 5, tile = blk & 31;

    for (int i = t; i < FLEN; i += 256) fs[i] = g_feat[b*FLEN + i];
    if (t < DKK) { gs[t] = gamma[t]; bs[t] = beta[t]; }
    __syncthreads();

    const int i = tile*TILE + (t >> 1);
    const int half = t & 1;
    const size_t tok = (size_t)b*NN + i;

    float q = g_Q[tok];
    float s1, c1;
    __sincosf(OMEGA1 * q, &s1, &c1);
    float c = 1.f, s = 0.f;

    float num[32];
    #pragma unroll
    for (int k = 0; k < 32; k++) num[k] = 0.f;
    float den = 0.f;

    for (int m = 0; m < MT; m++) {
        float wc = ca.a[m] * c;
        float ws = ca.a[m] * s;
        const float* bse = fs + m*FSTRIDE;
        den = fmaf(wc, bse[128], den);
        den = fmaf(ws, bse[129], den);
        const float4* C4 = (const float4*)&bse[half*32];
        const float4* S4 = (const float4*)&bse[64 + half*32];
        #pragma unroll
        for (int k4 = 0; k4 < 8; k4++) {
            float4 C = C4[k4];
            float4 S = S4[k4];
            num[k4*4+0] = fmaf(wc, C.x, fmaf(ws, S.x, num[k4*4+0]));
            num[k4*4+1] = fmaf(wc, C.y, fmaf(ws, S.y, num[k4*4+1]));
            num[k4*4+2] = fmaf(wc, C.z, fmaf(ws, S.z, num[k4*4+2]));
            num[k4*4+3] = fmaf(wc, C.w, fmaf(ws, S.w, num[k4*4+3]));
        }
        float cn = c*c1 - s*s1;
        s = fmaf(s, c1, c*s1);
        c = cn;
    }

    // epilogue: out = num/den + x, then LayerNorm (pair of threads = one token)
    const float* xr = x + tok*DKK + half*32;
    float invden = 1.f / den;
    float psum = 0.f;
    #pragma unroll
    for (int k = 0; k < 32; k++) {
        num[k] = fmaf(num[k], invden, xr[k]);
        psum += num[k];
    }
    psum += __shfl_xor_sync(0xffffffffu, psum, 1);
    float mu = psum * (1.f/64.f);
    float pvar = 0.f;
    #pragma unroll
    for (int k = 0; k < 32; k++) {
        float dd = num[k] - mu;
        pvar = fmaf(dd, dd, pvar);
    }
    pvar += __shfl_xor_sync(0xffffffffu, pvar, 1);
    float rstd = rsqrtf(pvar*(1.f/64.f) + 1e-5f);

    float* orow = out + tok*DKK + half*32;
    #pragma unroll
    for (int k = 0; k < 32; k++)
        orow[k] = (num[k] - mu) * rstd * gs[half*32 + k] + bs[half*32 + k];
}

// ---------------------------------------------------------------------------
extern "C" void kernel_launch(void* const* d_in, const int* in_sizes, int n_in,
                              void* d_out, int out_size)
{
    const float* x     = (const float*)d_in[0];
    const float* Wv    = (const float*)d_in[1];
    const float* bv    = (const float*)d_in[2];
    const float* wq    = (const float*)d_in[3];
    const float* wk    = (const float*)d_in[4];
    const float* gamma = (const float*)d_in[5];
    const float* beta  = (const float*)d_in[6];
    float* out = (float*)d_out;

    // Fourier cosine coefficients of g(t)=exp(exp(-t^2)/8) on [-T,T],
    // computed in double on the host (runs at capture time only; graph
    // replays carry these as baked kernel params).
    CoefArg ca;
    {
        const int P = 8192;
        const double T = THALF, L = 2.0*T;
        for (int m = 0; m < MT; m++) {
            double w = 3.14159265358979323846 * (double)m / T;
            double sum = 0.0;
            for (int p = 0; p < P; p++) {
                double tt = -T + (p + 0.5) * (L / P);
                sum += exp(exp(-tt*tt) * 0.125) * cos(w * tt);
            }
            ca.a[m] = (float)(((m == 0) ? 1.0 : 2.0) * sum / (double)P);
        }
    }

    const size_t sm1 = (size_t)(TILE*65 + 64*68 + TILE*68 + 2*MT*129 + 3*64) * sizeof(float);
    const size_t sm2 = (size_t)(FLEN + 128) * sizeof(float);
    cudaFuncSetAttribute(k_feat, cudaFuncAttributeMaxDynamicSharedMemorySize, (int)sm1);
    cudaFuncSetAttribute(k_out,  cudaFuncAttributeMaxDynamicSharedMemorySize, (int)sm2);

    k_feat<<<NBLK, 256, sm1>>>(x, Wv, bv, wq, wk);
    k_reduce<<<dim3((FLEN + 255)/256, BB), 256>>>();
    k_out<<<NBLK, 256, sm2>>>(x, gamma, beta, out, ca);
}

// round 2
// speedup vs baseline: 1.0006x; 1.0006x over previous
#include <cuda_runtime.h>
#include <math.h>

#define BB 4
#define NN 4096
#define DKK 64
#define MT 20                       // Fourier modes (truncation err ~6e-6 abs)
#define THALF 8.0                   // half-period T
#define OMEGA1 0.39269908169872414f // pi/8
#define TILE 64
#define NBLK 256                    // BB*NN/TILE
#define FSTRIDE 132                 // per-mode row: C[64], S[64], cc, ss, pad2
#define FLEN (MT*FSTRIDE)           // 2640

struct CoefArg { float a[MT]; };

__device__ __align__(16) float g_Q[BB*NN];
__device__ __align__(16) float g_part[(size_t)NBLK*FLEN];
__device__ __align__(16) float g_feat[BB*FLEN];

// ---------------------------------------------------------------------------
// K1: per-tile QKV + Fourier feature partial sums
// grid=256, block=320 (10 warps), smem ~61KB -> 3 CTAs/SM
// ---------------------------------------------------------------------------
__global__ __launch_bounds__(320, 3) void k_feat(
    const float* __restrict__ x, const float* __restrict__ Wv,
    const float* __restrict__ bv, const float* __restrict__ wq,
    const float* __restrict__ wk)
{
    extern __shared__ float sm[];
    float* xs   = sm;                    // TILE*65   = 4160
    float* Wvt  = xs  + TILE*65;         // 64*68     = 4352 (transposed, padded)
    float* Vs   = Wvt + 64*68;           // TILE*68   = 4352
    float* cosT = Vs  + TILE*68;         // MT*65     = 1300
    float* sinT = cosT + MT*65;          // MT*65     = 1300
    float* wqs  = sinT + MT*65;          // 64
    float* wks  = wqs + 64;              // 64
    float* bvs  = wks + 64;              // 64

    const int t = threadIdx.x;
    const int blk = blockIdx.x;
    const int b = blk >> 6, tile = blk & 63;
    const float* xt = x + ((size_t)b*NN + (size_t)tile*TILE) * DKK;

    // stage x tile (row stride 65)
    for (int i = t; i < TILE*DKK; i += 320)
        xs[(i >> 6)*65 + (i & 63)] = xt[i];
    // stage Wv transposed: Wvt[d][e] = Wv[e][d], row stride 68 (16B rows)
    for (int i = t; i < DKK*DKK; i += 320)
        Wvt[(i & 63)*68 + (i >> 6)] = Wv[i];
    if (t < DKK) { wqs[t] = wq[t]; wks[t] = wk[t]; bvs[t] = bv[t]; }
    __syncthreads();

    // per-token scalars Q,K + cos/sin tables via rotation recurrence
    if (t < TILE) {
        float q = 0.f, k = 0.f;
        #pragma unroll 16
        for (int d = 0; d < DKK; d++) {
            float xv = xs[t*65 + d];
            q = fmaf(xv, wqs[d], q);
            k = fmaf(xv, wks[d], k);
        }
        g_Q[(size_t)b*NN + (size_t)tile*TILE + t] = q;
        float s1, c1;
        __sincosf(OMEGA1 * k, &s1, &c1);
        float c = 1.f, s = 0.f;
        #pragma unroll
        for (int m = 0; m < MT; m++) {
            cosT[m*65 + t] = c;
            sinT[m*65 + t] = s;
            float cn = c*c1 - s*s1;
            s = fmaf(s, c1, c*s1);
            c = cn;
        }
    }

    // V = x @ Wv^T + bv  (t<256: token j = t>>2, quarter q owns 16 outputs)
    if (t < 256) {
        const int j = t >> 2, qq = t & 3;
        float acc[16];
        #pragma unroll
        for (int i = 0; i < 16; i++) acc[i] = bvs[qq*16 + i];
        #pragma unroll 4
        for (int d2 = 0; d2 < DKK; d2++) {
            float xv = xs[j*65 + d2];
            const float4* wrow = (const float4*)&Wvt[d2*68 + qq*16];
            #pragma unroll
            for (int i4 = 0; i4 < 4; i4++) {
                float4 w4 = wrow[i4];
                acc[i4*4+0] = fmaf(xv, w4.x, acc[i4*4+0]);
                acc[i4*4+1] = fmaf(xv, w4.y, acc[i4*4+1]);
                acc[i4*4+2] = fmaf(xv, w4.z, acc[i4*4+2]);
                acc[i4*4+3] = fmaf(xv, w4.w, acc[i4*4+3]);
            }
        }
        float4* vrow = (float4*)&Vs[j*68 + qq*16];
        #pragma unroll
        for (int i4 = 0; i4 < 4; i4++)
            vrow[i4] = make_float4(acc[i4*4+0], acc[i4*4+1], acc[i4*4+2], acc[i4*4+3]);
    }
    __syncthreads();

    // feature rank-update: thread = (d4 in 0..15, m in 0..19), 1 mode each
    {
        const int d4 = t & 15, m = t >> 4;
        float aC0=0,aC1=0,aC2=0,aC3=0, aS0=0,aS1=0,aS2=0,aS3=0;
        float aCC = 0.f, aSS = 0.f;
        #pragma unroll 4
        for (int j = 0; j < TILE; j++) {
            float4 v = *(const float4*)&Vs[j*68 + d4*4];
            float c = cosT[m*65 + j];
            float s = sinT[m*65 + j];
            aC0 = fmaf(c, v.x, aC0); aC1 = fmaf(c, v.y, aC1);
            aC2 = fmaf(c, v.z, aC2); aC3 = fmaf(c, v.w, aC3);
            aS0 = fmaf(s, v.x, aS0); aS1 = fmaf(s, v.y, aS1);
            aS2 = fmaf(s, v.z, aS2); aS3 = fmaf(s, v.w, aS3);
            aCC += c; aSS += s;
        }
        float* bse = g_part + (size_t)blk * FLEN + m*FSTRIDE;
        *(float4*)&bse[d4*4]      = make_float4(aC0, aC1, aC2, aC3);
        *(float4*)&bse[64 + d4*4] = make_float4(aS0, aS1, aS2, aS3);
        if (d4 == 0) { bse[128] = aCC; bse[129] = aSS; }
    }
}

// ---------------------------------------------------------------------------
// K1b: reduce 64 tile-partials per batch (deterministic, no atomics)
// ---------------------------------------------------------------------------
__global__ __launch_bounds__(256) void k_reduce()
{
    int f = blockIdx.x * 256 + threadIdx.x;
    int b = blockIdx.y;
    if (f >= FLEN) return;
    float s = 0.f;
    #pragma unroll 8
    for (int tb = 0; tb < 64; tb++)
        s += g_part[(size_t)(b*64 + tb)*FLEN + f];
    g_feat[b*FLEN + f] = s;
}

// ---------------------------------------------------------------------------
// K2: per-token output = softmax-weighted V-sum (via features) + residual + LN
// grid=256, block=128 (2 threads per token), smem ~11KB
// ---------------------------------------------------------------------------
__global__ __launch_bounds__(128) void k_out(
    const float* __restrict__ x, const float* __restrict__ gamma,
    const float* __restrict__ beta, float* __restrict__ out, CoefArg ca)
{
    extern __shared__ float sm[];
    float* fs = sm;            // FLEN
    float* gs = fs + FLEN;     // 64
    float* bs = gs + 64;       // 64

    const int t = threadIdx.x;
    const int blk = blockIdx.x;
    const int b = blk >> 6, tile = blk & 63;

    for (int i = t; i < FLEN; i += 128) fs[i] = g_feat[b*FLEN + i];
    if (t < DKK) { gs[t] = gamma[t]; bs[t] = beta[t]; }
    __syncthreads();

    const int i = tile*TILE + (t >> 1);
    const int half = t & 1;
    const size_t tok = (size_t)b*NN + i;

    float q = g_Q[tok];
    float s1, c1;
    __sincosf(OMEGA1 * q, &s1, &c1);
    float c = 1.f, s = 0.f;

    float num[32];
    #pragma unroll
    for (int k = 0; k < 32; k++) num[k] = 0.f;
    float den = 0.f;

    #pragma unroll 4
    for (int m = 0; m < MT; m++) {
        float wc = ca.a[m] * c;
        float ws = ca.a[m] * s;
        const float* bse = fs + m*FSTRIDE;
        den = fmaf(wc, bse[128], den);
        den = fmaf(ws, bse[129], den);
        const float4* C4 = (const float4*)&bse[half*32];
        const float4* S4 = (const float4*)&bse[64 + half*32];
        #pragma unroll
        for (int k4 = 0; k4 < 8; k4++) {
            float4 C = C4[k4];
            float4 S = S4[k4];
            num[k4*4+0] = fmaf(wc, C.x, fmaf(ws, S.x, num[k4*4+0]));
            num[k4*4+1] = fmaf(wc, C.y, fmaf(ws, S.y, num[k4*4+1]));
            num[k4*4+2] = fmaf(wc, C.z, fmaf(ws, S.z, num[k4*4+2]));
            num[k4*4+3] = fmaf(wc, C.w, fmaf(ws, S.w, num[k4*4+3]));
        }
        float cn = c*c1 - s*s1;
        s = fmaf(s, c1, c*s1);
        c = cn;
    }

    // epilogue: out = num/den + x, then LayerNorm (pair of threads = one token)
    const float* xr = x + tok*DKK + half*32;
    float invden = 1.f / den;
    float psum = 0.f;
    #pragma unroll
    for (int k = 0; k < 32; k++) {
        num[k] = fmaf(num[k], invden, xr[k]);
        psum += num[k];
    }
    psum += __shfl_xor_sync(0xffffffffu, psum, 1);
    float mu = psum * (1.f/64.f);
    float pvar = 0.f;
    #pragma unroll
    for (int k = 0; k < 32; k++) {
        float dd = num[k] - mu;
        pvar = fmaf(dd, dd, pvar);
    }
    pvar += __shfl_xor_sync(0xffffffffu, pvar, 1);
    float rstd = rsqrtf(pvar*(1.f/64.f) + 1e-5f);

    float* orow = out + tok*DKK + half*32;
    #pragma unroll
    for (int k = 0; k < 32; k++)
        orow[k] = (num[k] - mu) * rstd * gs[half*32 + k] + bs[half*32 + k];
}

// ---------------------------------------------------------------------------
extern "C" void kernel_launch(void* const* d_in, const int* in_sizes, int n_in,
                              void* d_out, int out_size)
{
    const float* x     = (const float*)d_in[0];
    const float* Wv    = (const float*)d_in[1];
    const float* bv    = (const float*)d_in[2];
    const float* wq    = (const float*)d_in[3];
    const float* wk    = (const float*)d_in[4];
    const float* gamma = (const float*)d_in[5];
    const float* beta  = (const float*)d_in[6];
    float* out = (float*)d_out;

    // Fourier cosine coefficients of g(t)=exp(exp(-t^2)/8) on [-T,T],
    // computed in double on the host (capture-time only; graph replays
    // carry these as baked kernel params).
    CoefArg ca;
    {
        const int P = 8192;
        const double T = THALF, L = 2.0*T;
        for (int m = 0; m < MT; m++) {
            double w = 3.14159265358979323846 * (double)m / T;
            double sum = 0.0;
            for (int p = 0; p < P; p++) {
                double tt = -T + (p + 0.5) * (L / P);
                sum += exp(exp(-tt*tt) * 0.125) * cos(w * tt);
            }
            ca.a[m] = (float)(((m == 0) ? 1.0 : 2.0) * sum / (double)P);
        }
    }

    const size_t sm1 = (size_t)(TILE*65 + 64*68 + TILE*68 + 2*MT*65 + 3*64) * sizeof(float);
    const size_t sm2 = (size_t)(FLEN + 128) * sizeof(float);
    cudaFuncSetAttribute(k_feat, cudaFuncAttributeMaxDynamicSharedMemorySize, (int)sm1);
    cudaFuncSetAttribute(k_out,  cudaFuncAttributeMaxDynamicSharedMemorySize, (int)sm2);

    k_feat<<<NBLK, 320, sm1>>>(x, Wv, bv, wq, wk);
    k_reduce<<<dim3((FLEN + 255)/256, BB), 256>>>();
    k_out<<<NBLK, 128, sm2>>>(x, gamma, beta, out, ca);
}